// round 8
// baseline (speedup 1.0000x reference)
#include <cuda_runtime.h>
#include <math.h>
#include <stdint.h>

#define DM   768
#define NH   12
#define DK   64
#define BATCH 4
#define SEQ  2048
#define MTOT (BATCH*SEQ)   // 8192

// Scratch (device globals: allocation-free).
__device__ float g_q[(size_t)MTOT*DM];
__device__ float g_k[(size_t)MTOT*DM];
__device__ float g_v[(size_t)MTOT*DM];
__device__ float g_attn[(size_t)MTOT*DM];

// ---------------------------------------------------------------------------
// tf32 helpers
// ---------------------------------------------------------------------------
__device__ __forceinline__ uint32_t f2tf32(float x) {
    uint32_t r;
    asm("cvt.rna.tf32.f32 %0, %1;" : "=r"(r) : "f"(x));
    return r;
}

__device__ __forceinline__ void mma_tf32(float (&d)[4], const uint32_t (&a)[4],
                                         const uint32_t (&b)[2]) {
    asm volatile(
        "mma.sync.aligned.m16n8k8.row.col.f32.tf32.tf32.f32 "
        "{%0,%1,%2,%3}, {%4,%5,%6,%7}, {%8,%9}, {%0,%1,%2,%3};"
        : "+f"(d[0]), "+f"(d[1]), "+f"(d[2]), "+f"(d[3])
        : "r"(a[0]), "r"(a[1]), "r"(a[2]), "r"(a[3]), "r"(b[0]), "r"(b[1]));
}

// ---------------------------------------------------------------------------
// Split-precision tf32 GEMM: C = A(M x 768) @ W(768 x 768) + bias.
// (unchanged from R4)
// ---------------------------------------------------------------------------
#define LDA 136

template<bool HEAD_SPLIT>
__global__ __launch_bounds__(256)
void gemm_tf32(const float* __restrict__ A, const float* __restrict__ W,
               const float* __restrict__ bias, float* __restrict__ C)
{
    const int BM = 128, BN = 128, BK = 32;
    extern __shared__ float sm[];
    float* Ah = sm;
    float* Al = Ah + BK * LDA;
    float* Bh = Al + BK * LDA;
    float* Bl = Bh + BK * LDA;

    const int bm = blockIdx.y * BM;
    const int bn = blockIdx.x * BN;
    const int tid  = threadIdx.x;
    const int lane = tid & 31;
    const int w    = tid >> 5;
    const int grp  = lane >> 2;
    const int tig  = lane & 3;
    const int wm   = (w & 1) * 64;
    const int wn   = (w >> 1) * 32;

    float acc[4][4][4];
#pragma unroll
    for (int mi = 0; mi < 4; mi++)
#pragma unroll
        for (int ni = 0; ni < 4; ni++)
#pragma unroll
            for (int e = 0; e < 4; e++) acc[mi][ni][e] = 0.f;

    const int ar = tid >> 1;
    const int ac = (tid & 1) * 16;
    const int br = tid >> 3;
    const int bc = (tid & 7) * 16;

    for (int k0 = 0; k0 < DM; k0 += BK) {
#pragma unroll
        for (int p = 0; p < 4; p++) {
            float4 v = *(const float4*)(A + (size_t)(bm + ar) * DM + k0 + ac + p * 4);
            float vv[4] = {v.x, v.y, v.z, v.w};
#pragma unroll
            for (int q = 0; q < 4; q++) {
                const int k = ac + p * 4 + q;
                const float hf = __uint_as_float(f2tf32(vv[q]));
                Ah[k * LDA + ar] = hf;
                Al[k * LDA + ar] = vv[q] - hf;
            }
        }
#pragma unroll
        for (int p = 0; p < 4; p++) {
            float4 v = *(const float4*)(W + (size_t)(k0 + br) * DM + bn + bc + p * 4);
            float vv[4] = {v.x, v.y, v.z, v.w};
#pragma unroll
            for (int q = 0; q < 4; q++) {
                const float hf = __uint_as_float(f2tf32(vv[q]));
                Bh[br * LDA + bc + p * 4 + q] = hf;
                Bl[br * LDA + bc + p * 4 + q] = vv[q] - hf;
            }
        }
        __syncthreads();

#pragma unroll
        for (int ks = 0; ks < BK; ks += 8) {
            uint32_t a_h[4][4], a_l[4][4], b_h[4][2], b_l[4][2];
#pragma unroll
            for (int mi = 0; mi < 4; mi++) {
                const int m0 = wm + mi * 16 + grp;
                const int r0 = (ks + tig) * LDA;
                const int r4 = (ks + tig + 4) * LDA;
                a_h[mi][0] = __float_as_uint(Ah[r0 + m0]);
                a_h[mi][1] = __float_as_uint(Ah[r0 + m0 + 8]);
                a_h[mi][2] = __float_as_uint(Ah[r4 + m0]);
                a_h[mi][3] = __float_as_uint(Ah[r4 + m0 + 8]);
                a_l[mi][0] = __float_as_uint(Al[r0 + m0]);
                a_l[mi][1] = __float_as_uint(Al[r0 + m0 + 8]);
                a_l[mi][2] = __float_as_uint(Al[r4 + m0]);
                a_l[mi][3] = __float_as_uint(Al[r4 + m0 + 8]);
            }
#pragma unroll
            for (int ni = 0; ni < 4; ni++) {
                const int n0 = wn + ni * 8 + grp;
                b_h[ni][0] = __float_as_uint(Bh[(ks + tig) * LDA + n0]);
                b_h[ni][1] = __float_as_uint(Bh[(ks + tig + 4) * LDA + n0]);
                b_l[ni][0] = __float_as_uint(Bl[(ks + tig) * LDA + n0]);
                b_l[ni][1] = __float_as_uint(Bl[(ks + tig + 4) * LDA + n0]);
            }
#pragma unroll
            for (int mi = 0; mi < 4; mi++)
#pragma unroll
                for (int ni = 0; ni < 4; ni++) {
                    mma_tf32(acc[mi][ni], a_h[mi], b_h[ni]);
                    mma_tf32(acc[mi][ni], a_h[mi], b_l[ni]);
                    mma_tf32(acc[mi][ni], a_l[mi], b_h[ni]);
                }
        }
        __syncthreads();
    }

#pragma unroll
    for (int mi = 0; mi < 4; mi++) {
#pragma unroll
        for (int ni = 0; ni < 4; ni++) {
#pragma unroll
            for (int e = 0; e < 4; e++) {
                const int m = bm + wm + mi * 16 + grp + (e >> 1) * 8;
                const int n = bn + wn + ni * 8 + tig * 2 + (e & 1);
                const float v = acc[mi][ni][e] + bias[n];
                if (HEAD_SPLIT) {
                    const int bb = m >> 11, ss = m & (SEQ - 1);
                    const int hh = n >> 6,  dd = n & (DK - 1);
                    C[((size_t)(bb * NH + hh) * SEQ + ss) * DK + dd] = v;
                } else {
                    C[(size_t)m * DM + n] = v;
                }
            }
        }
    }
}

// ---------------------------------------------------------------------------
// Tensor-core flash attention (causal, online softmax, split-tf32 MMA).
// Block = (b, h, 128-row q tile); 8 warps as 4(m) x 2(n); 32x32 warp tiles.
// ---------------------------------------------------------------------------
#define QT   128
#define KT   64
#define APAD 68

__global__ __launch_bounds__(256)
void attn_mma()
{
    extern __shared__ float sm[];
    float* Qh = sm;                       // 128 x 68
    float* Ql = Qh + QT * APAD;
    float* Kh = Ql + QT * APAD;           // 64 x 68
    float* Kl = Kh + KT * APAD;
    float* Vh = Kl + KT * APAD;           // 64 x 68
    float* Vl = Vh + KT * APAD;
    float* Ph = Vl + KT * APAD;           // 128 x 68
    float* Pl = Ph + QT * APAD;
    float* redm = Pl + QT * APAD;         // 2 x 128
    float* reds = redm + 2 * QT;          // 2 x 128

    const int qi = (SEQ / QT - 1) - blockIdx.x;   // heavy tiles first (LPT)
    const int h  = blockIdx.y;
    const int b  = blockIdx.z;
    const int tid  = threadIdx.x;
    const int lane = tid & 31;
    const int w    = tid >> 5;
    const int grp  = lane >> 2;
    const int tig  = lane & 3;
    const int wm   = (w & 3) * 32;        // warp m offset (0..96)
    const int wn   = (w >> 2) * 32;       // warp n offset (0 or 32)
    const int warp_n = w >> 2;

    const float* Qg = g_q + ((size_t)(b * NH + h) * SEQ + (size_t)qi * QT) * DK;
    const float* Kg = g_k + (size_t)(b * NH + h) * SEQ * DK;
    const float* Vg = g_v + (size_t)(b * NH + h) * SEQ * DK;

    // ---- load Q tile (128 x 64), split hi/lo ----
    {
        const int r  = tid >> 1;
        const int c0 = (tid & 1) * 32;
#pragma unroll
        for (int p = 0; p < 8; p++) {
            float4 v = *(const float4*)(Qg + (size_t)r * DK + c0 + p * 4);
            float vv[4] = {v.x, v.y, v.z, v.w};
#pragma unroll
            for (int q = 0; q < 4; q++) {
                const float hf = __uint_as_float(f2tf32(vv[q]));
                Qh[r * APAD + c0 + p * 4 + q] = hf;
                Ql[r * APAD + c0 + p * 4 + q] = vv[q] - hf;
            }
        }
    }

    float m_i[2][2], l_i[2][2], o[2][4][4];
#pragma unroll
    for (int mi = 0; mi < 2; mi++)
#pragma unroll
        for (int hf = 0; hf < 2; hf++) { m_i[mi][hf] = -INFINITY; l_i[mi][hf] = 0.f; }
#pragma unroll
    for (int mi = 0; mi < 2; mi++)
#pragma unroll
        for (int ni = 0; ni < 4; ni++)
#pragma unroll
            for (int e = 0; e < 4; e++) o[mi][ni][e] = 0.f;

    const float scale = 0.125f;   // 1/sqrt(64)
    const int jmax = 2 * qi + 1;

    for (int j = 0; j <= jmax; j++) {
        __syncthreads();   // Q load done (iter 0) / prev PV readers done

        // ---- load K,V tiles (64 x 64), split hi/lo ----
        {
            const int r  = tid >> 2;
            const int c0 = (tid & 3) * 16;
#pragma unroll
            for (int p = 0; p < 4; p++) {
                float4 kv = *(const float4*)(Kg + (size_t)(j * KT + r) * DK + c0 + p * 4);
                float4 vv = *(const float4*)(Vg + (size_t)(j * KT + r) * DK + c0 + p * 4);
                float kk[4] = {kv.x, kv.y, kv.z, kv.w};
                float vf[4] = {vv.x, vv.y, vv.z, vv.w};
#pragma unroll
                for (int q = 0; q < 4; q++) {
                    const int c = c0 + p * 4 + q;
                    float hk = __uint_as_float(f2tf32(kk[q]));
                    Kh[r * APAD + c] = hk;
                    Kl[r * APAD + c] = kk[q] - hk;
                    float hv = __uint_as_float(f2tf32(vf[q]));
                    Vh[r * APAD + c] = hv;
                    Vl[r * APAD + c] = vf[q] - hv;
                }
            }
        }
        __syncthreads();

        // ---- S = Q K^T (split tf32) ----
        float s[2][4][4];
#pragma unroll
        for (int mi = 0; mi < 2; mi++)
#pragma unroll
            for (int ni = 0; ni < 4; ni++)
#pragma unroll
                for (int e = 0; e < 4; e++) s[mi][ni][e] = 0.f;

#pragma unroll
        for (int ks = 0; ks < 8; ks++) {
            const int kc = ks * 8 + tig;
            uint32_t ah[2][4], al[2][4];
#pragma unroll
            for (int mi = 0; mi < 2; mi++) {
                const int r0 = wm + mi * 16 + grp;
                ah[mi][0] = __float_as_uint(Qh[r0 * APAD + kc]);
                ah[mi][1] = __float_as_uint(Qh[(r0 + 8) * APAD + kc]);
                ah[mi][2] = __float_as_uint(Qh[r0 * APAD + kc + 4]);
                ah[mi][3] = __float_as_uint(Qh[(r0 + 8) * APAD + kc + 4]);
                al[mi][0] = __float_as_uint(Ql[r0 * APAD + kc]);
                al[mi][1] = __float_as_uint(Ql[(r0 + 8) * APAD + kc]);
                al[mi][2] = __float_as_uint(Ql[r0 * APAD + kc + 4]);
                al[mi][3] = __float_as_uint(Ql[(r0 + 8) * APAD + kc + 4]);
            }
#pragma unroll
            for (int ni = 0; ni < 4; ni++) {
                const int n0 = wn + ni * 8 + grp;
                uint32_t bh[2], bl[2];
                bh[0] = __float_as_uint(Kh[n0 * APAD + kc]);
                bh[1] = __float_as_uint(Kh[n0 * APAD + kc + 4]);
                bl[0] = __float_as_uint(Kl[n0 * APAD + kc]);
                bl[1] = __float_as_uint(Kl[n0 * APAD + kc + 4]);
#pragma unroll
                for (int mi = 0; mi < 2; mi++) {
                    mma_tf32(s[mi][ni], ah[mi], bh);
                    mma_tf32(s[mi][ni], ah[mi], bl);
                    mma_tf32(s[mi][ni], al[mi], bh);
                }
            }
        }

        // ---- scale + causal mask ----
        const bool need_mask = (j >= 2 * qi);
#pragma unroll
        for (int mi = 0; mi < 2; mi++)
#pragma unroll
            for (int ni = 0; ni < 4; ni++)
#pragma unroll
                for (int e = 0; e < 4; e++) {
                    float v = s[mi][ni][e] * scale;
                    if (need_mask) {
                        const int gr = qi * QT + wm + mi * 16 + grp + (e >> 1) * 8;
                        const int gc = j * KT + wn + ni * 8 + tig * 2 + (e & 1);
                        if (gc > gr) v = -INFINITY;
                    }
                    s[mi][ni][e] = v;
                }

        // ---- row max (quad shfl + cross-warp smem) ----
        float rmax[2][2];
#pragma unroll
        for (int mi = 0; mi < 2; mi++)
#pragma unroll
            for (int hf = 0; hf < 2; hf++) {
                float rm = -INFINITY;
#pragma unroll
                for (int ni = 0; ni < 4; ni++)
                    rm = fmaxf(rm, fmaxf(s[mi][ni][hf * 2], s[mi][ni][hf * 2 + 1]));
                rm = fmaxf(rm, __shfl_xor_sync(0xffffffffu, rm, 1));
                rm = fmaxf(rm, __shfl_xor_sync(0xffffffffu, rm, 2));
                rmax[mi][hf] = rm;
                if (tig == 0)
                    redm[warp_n * QT + wm + mi * 16 + grp + hf * 8] = rm;
            }
        __syncthreads();

        // ---- combine max, exp, local sums, P hi/lo write ----
        float alpha_s[2][2];
#pragma unroll
        for (int mi = 0; mi < 2; mi++)
#pragma unroll
            for (int hf = 0; hf < 2; hf++) {
                const int rl = wm + mi * 16 + grp + hf * 8;
                const float nm = fmaxf(m_i[mi][hf], fmaxf(redm[rl], redm[QT + rl]));
                const float alpha = __expf(m_i[mi][hf] - nm);
                m_i[mi][hf] = nm;
                alpha_s[mi][hf] = alpha;
                float rs = 0.f;
#pragma unroll
                for (int ni = 0; ni < 4; ni++) {
                    float p0 = __expf(s[mi][ni][hf * 2 + 0] - nm);
                    float p1 = __expf(s[mi][ni][hf * 2 + 1] - nm);
                    s[mi][ni][hf * 2 + 0] = p0;
                    s[mi][ni][hf * 2 + 1] = p1;
                    rs += p0 + p1;
                }
                rs += __shfl_xor_sync(0xffffffffu, rs, 1);
                rs += __shfl_xor_sync(0xffffffffu, rs, 2);
                if (tig == 0)
                    reds[warp_n * QT + rl] = rs;
                l_i[mi][hf] *= alpha;
#pragma unroll
                for (int ni = 0; ni < 4; ni++) {
                    o[mi][ni][hf * 2 + 0] *= alpha;
                    o[mi][ni][hf * 2 + 1] *= alpha;
                }
            }

        // P -> smem (hi/lo)
#pragma unroll
        for (int mi = 0; mi < 2; mi++)
#pragma unroll
            for (int ni = 0; ni < 4; ni++)
#pragma unroll
                for (int hf = 0; hf < 2; hf++) {
                    const int row = wm + mi * 16 + grp + hf * 8;
                    const int col = wn + ni * 8 + tig * 2;
                    const float p0 = s[mi][ni][hf * 2 + 0];
                    const float p1 = s[mi][ni][hf * 2 + 1];
                    const float h0 = __uint_as_float(f2tf32(p0));
                    const float h1 = __uint_as_float(f2tf32(p1));
                    *(float2*)&Ph[row * APAD + col] = make_float2(h0, h1);
                    *(float2*)&Pl[row * APAD + col] = make_float2(p0 - h0, p1 - h1);
                }
        __syncthreads();

#pragma unroll
        for (int mi = 0; mi < 2; mi++)
#pragma unroll
            for (int hf = 0; hf < 2; hf++) {
                const int rl = wm + mi * 16 + grp + hf * 8;
                l_i[mi][hf] += reds[rl] + reds[QT + rl];
            }

        // ---- O += P V (split tf32) ----
#pragma unroll
        for (int ks = 0; ks < 8; ks++) {
            const int kc = ks * 8 + tig;
            uint32_t ah[2][4], al[2][4];
#pragma unroll
            for (int mi = 0; mi < 2; mi++) {
                const int r0 = wm + mi * 16 + grp;
                ah[mi][0] = __float_as_uint(Ph[r0 * APAD + kc]);
                ah[mi][1] = __float_as_uint(Ph[(r0 + 8) * APAD + kc]);
                ah[mi][2] = __float_as_uint(Ph[r0 * APAD + kc + 4]);
                ah[mi][3] = __float_as_uint(Ph[(r0 + 8) * APAD + kc + 4]);
                al[mi][0] = __float_as_uint(Pl[r0 * APAD + kc]);
                al[mi][1] = __float_as_uint(Pl[(r0 + 8) * APAD + kc]);
                al[mi][2] = __float_as_uint(Pl[r0 * APAD + kc + 4]);
                al[mi][3] = __float_as_uint(Pl[(r0 + 8) * APAD + kc + 4]);
            }
#pragma unroll
            for (int ni = 0; ni < 4; ni++) {
                const int n0 = wn + ni * 8 + grp;
                uint32_t bh[2], bl[2];
                bh[0] = __float_as_uint(Vh[(ks * 8 + tig) * APAD + n0]);
                bh[1] = __float_as_uint(Vh[(ks * 8 + tig + 4) * APAD + n0]);
                bl[0] = __float_as_uint(Vl[(ks * 8 + tig) * APAD + n0]);
                bl[1] = __float_as_uint(Vl[(ks * 8 + tig + 4) * APAD + n0]);
#pragma unroll
                for (int mi = 0; mi < 2; mi++) {
                    mma_tf32(o[mi][ni], ah[mi], bh);
                    mma_tf32(o[mi][ni], ah[mi], bl);
                    mma_tf32(o[mi][ni], al[mi], bh);
                }
            }
        }
    }

    // ---- epilogue: normalize, write (B, S, D) layout ----
#pragma unroll
    for (int mi = 0; mi < 2; mi++)
#pragma unroll
        for (int hf = 0; hf < 2; hf++) {
            const float inv = 1.f / l_i[mi][hf];
            const int srow = qi * QT + wm + mi * 16 + grp + hf * 8;
#pragma unroll
            for (int ni = 0; ni < 4; ni++) {
                const int col = h * DK + wn + ni * 8 + tig * 2;
                float2 v = make_float2(o[mi][ni][hf * 2 + 0] * inv,
                                       o[mi][ni][hf * 2 + 1] * inv);
                *(float2*)&g_attn[((size_t)(b * SEQ) + srow) * DM + col] = v;
            }
        }
}

// ---------------------------------------------------------------------------

extern "C" void kernel_launch(void* const* d_in, const int* in_sizes, int n_in,
                              void* d_out, int out_size)
{
    const float* x  = (const float*)d_in[0];
    const float* Wq = (const float*)d_in[1];
    const float* bq = (const float*)d_in[2];
    const float* Wk = (const float*)d_in[3];
    const float* bk = (const float*)d_in[4];
    const float* Wv = (const float*)d_in[5];
    const float* bv = (const float*)d_in[6];
    const float* Wo = (const float*)d_in[7];
    const float* bo = (const float*)d_in[8];
    float* out = (float*)d_out;

    float *qp, *kp, *vp, *ap;
    cudaGetSymbolAddress((void**)&qp, g_q);
    cudaGetSymbolAddress((void**)&kp, g_k);
    cudaGetSymbolAddress((void**)&vp, g_v);
    cudaGetSymbolAddress((void**)&ap, g_attn);

    const dim3 ggrid(DM / 128, MTOT / 128);
    const int gemm_smem = 4 * 32 * LDA * (int)sizeof(float);

    cudaFuncSetAttribute(gemm_tf32<true>,  cudaFuncAttributeMaxDynamicSharedMemorySize, gemm_smem);
    cudaFuncSetAttribute(gemm_tf32<false>, cudaFuncAttributeMaxDynamicSharedMemorySize, gemm_smem);

    gemm_tf32<true><<<ggrid, 256, gemm_smem>>>(x, Wq, bq, qp);
    gemm_tf32<true><<<ggrid, 256, gemm_smem>>>(x, Wk, bk, kp);
    gemm_tf32<true><<<ggrid, 256, gemm_smem>>>(x, Wv, bv, vp);

    // attn smem: Q(2) + K(2) + V(2) + P(2) tiles + 2 reduce buffers
    const int attn_smem = (2 * QT * APAD + 4 * KT * APAD + 2 * QT * APAD + 4 * QT)
                          * (int)sizeof(float);   // 210,944 B
    cudaFuncSetAttribute(attn_mma, cudaFuncAttributeMaxDynamicSharedMemorySize,
                         attn_smem);
    attn_mma<<<dim3(SEQ / QT, NH, BATCH), 256, attn_smem>>>();

    gemm_tf32<false><<<ggrid, 256, gemm_smem>>>(ap, Wo, bo, out);
}

// round 9
// speedup vs baseline: 1.0020x; 1.0020x over previous
#include <cuda_runtime.h>
#include <math.h>
#include <stdint.h>

#define DM   768
#define NH   12
#define DK   64
#define BATCH 4
#define SEQ  2048
#define MTOT (BATCH*SEQ)   // 8192

// Scratch (device globals: allocation-free).
__device__ float g_q[(size_t)MTOT*DM];
__device__ float g_k[(size_t)MTOT*DM];
__device__ float g_v[(size_t)MTOT*DM];
__device__ float g_attn[(size_t)MTOT*DM];

// ---------------------------------------------------------------------------
// tf32 helpers
// ---------------------------------------------------------------------------
__device__ __forceinline__ uint32_t f2tf32(float x) {
    uint32_t r;
    asm("cvt.rna.tf32.f32 %0, %1;" : "=r"(r) : "f"(x));
    return r;
}

__device__ __forceinline__ void mma_tf32(float (&d)[4], const uint32_t (&a)[4],
                                         const uint32_t (&b)[2]) {
    asm volatile(
        "mma.sync.aligned.m16n8k8.row.col.f32.tf32.tf32.f32 "
        "{%0,%1,%2,%3}, {%4,%5,%6,%7}, {%8,%9}, {%0,%1,%2,%3};"
        : "+f"(d[0]), "+f"(d[1]), "+f"(d[2]), "+f"(d[3])
        : "r"(a[0]), "r"(a[1]), "r"(a[2]), "r"(a[3]), "r"(b[0]), "r"(b[1]));
}

// ---------------------------------------------------------------------------
// Split-precision tf32 GEMM: C = A(M x 768) @ W(768 x 768) + bias.
// (unchanged from R4)
// ---------------------------------------------------------------------------
#define LDA 136

template<bool HEAD_SPLIT>
__global__ __launch_bounds__(256)
void gemm_tf32(const float* __restrict__ A, const float* __restrict__ W,
               const float* __restrict__ bias, float* __restrict__ C)
{
    const int BM = 128, BN = 128, BK = 32;
    extern __shared__ float sm[];
    float* Ah = sm;
    float* Al = Ah + BK * LDA;
    float* Bh = Al + BK * LDA;
    float* Bl = Bh + BK * LDA;

    const int bm = blockIdx.y * BM;
    const int bn = blockIdx.x * BN;
    const int tid  = threadIdx.x;
    const int lane = tid & 31;
    const int w    = tid >> 5;
    const int grp  = lane >> 2;
    const int tig  = lane & 3;
    const int wm   = (w & 1) * 64;
    const int wn   = (w >> 1) * 32;

    float acc[4][4][4];
#pragma unroll
    for (int mi = 0; mi < 4; mi++)
#pragma unroll
        for (int ni = 0; ni < 4; ni++)
#pragma unroll
            for (int e = 0; e < 4; e++) acc[mi][ni][e] = 0.f;

    const int ar = tid >> 1;
    const int ac = (tid & 1) * 16;
    const int br = tid >> 3;
    const int bc = (tid & 7) * 16;

    for (int k0 = 0; k0 < DM; k0 += BK) {
#pragma unroll
        for (int p = 0; p < 4; p++) {
            float4 v = *(const float4*)(A + (size_t)(bm + ar) * DM + k0 + ac + p * 4);
            float vv[4] = {v.x, v.y, v.z, v.w};
#pragma unroll
            for (int q = 0; q < 4; q++) {
                const int k = ac + p * 4 + q;
                const float hf = __uint_as_float(f2tf32(vv[q]));
                Ah[k * LDA + ar] = hf;
                Al[k * LDA + ar] = vv[q] - hf;
            }
        }
#pragma unroll
        for (int p = 0; p < 4; p++) {
            float4 v = *(const float4*)(W + (size_t)(k0 + br) * DM + bn + bc + p * 4);
            float vv[4] = {v.x, v.y, v.z, v.w};
#pragma unroll
            for (int q = 0; q < 4; q++) {
                const float hf = __uint_as_float(f2tf32(vv[q]));
                Bh[br * LDA + bc + p * 4 + q] = hf;
                Bl[br * LDA + bc + p * 4 + q] = vv[q] - hf;
            }
        }
        __syncthreads();

#pragma unroll
        for (int ks = 0; ks < BK; ks += 8) {
            uint32_t a_h[4][4], a_l[4][4], b_h[4][2], b_l[4][2];
#pragma unroll
            for (int mi = 0; mi < 4; mi++) {
                const int m0 = wm + mi * 16 + grp;
                const int r0 = (ks + tig) * LDA;
                const int r4 = (ks + tig + 4) * LDA;
                a_h[mi][0] = __float_as_uint(Ah[r0 + m0]);
                a_h[mi][1] = __float_as_uint(Ah[r0 + m0 + 8]);
                a_h[mi][2] = __float_as_uint(Ah[r4 + m0]);
                a_h[mi][3] = __float_as_uint(Ah[r4 + m0 + 8]);
                a_l[mi][0] = __float_as_uint(Al[r0 + m0]);
                a_l[mi][1] = __float_as_uint(Al[r0 + m0 + 8]);
                a_l[mi][2] = __float_as_uint(Al[r4 + m0]);
                a_l[mi][3] = __float_as_uint(Al[r4 + m0 + 8]);
            }
#pragma unroll
            for (int ni = 0; ni < 4; ni++) {
                const int n0 = wn + ni * 8 + grp;
                b_h[ni][0] = __float_as_uint(Bh[(ks + tig) * LDA + n0]);
                b_h[ni][1] = __float_as_uint(Bh[(ks + tig + 4) * LDA + n0]);
                b_l[ni][0] = __float_as_uint(Bl[(ks + tig) * LDA + n0]);
                b_l[ni][1] = __float_as_uint(Bl[(ks + tig + 4) * LDA + n0]);
            }
#pragma unroll
            for (int mi = 0; mi < 4; mi++)
#pragma unroll
                for (int ni = 0; ni < 4; ni++) {
                    mma_tf32(acc[mi][ni], a_h[mi], b_h[ni]);
                    mma_tf32(acc[mi][ni], a_h[mi], b_l[ni]);
                    mma_tf32(acc[mi][ni], a_l[mi], b_h[ni]);
                }
        }
        __syncthreads();
    }

#pragma unroll
    for (int mi = 0; mi < 4; mi++) {
#pragma unroll
        for (int ni = 0; ni < 4; ni++) {
#pragma unroll
            for (int e = 0; e < 4; e++) {
                const int m = bm + wm + mi * 16 + grp + (e >> 1) * 8;
                const int n = bn + wn + ni * 8 + tig * 2 + (e & 1);
                const float v = acc[mi][ni][e] + bias[n];
                if (HEAD_SPLIT) {
                    const int bb = m >> 11, ss = m & (SEQ - 1);
                    const int hh = n >> 6,  dd = n & (DK - 1);
                    C[((size_t)(bb * NH + hh) * SEQ + ss) * DK + dd] = v;
                } else {
                    C[(size_t)m * DM + n] = v;
                }
            }
        }
    }
}

// ---------------------------------------------------------------------------
// Tensor-core flash attention (causal, online softmax, split-tf32 MMA).
// Block = (b, h, 128-row q tile); 8 warps as 4(m) x 2(n); 32x32 warp tiles.
// ---------------------------------------------------------------------------
#define QT   128
#define KT   64
#define APAD 68

__global__ __launch_bounds__(256)
void attn_mma()
{
    extern __shared__ float sm[];
    float* Qh = sm;                       // 128 x 68
    float* Ql = Qh + QT * APAD;
    float* Kh = Ql + QT * APAD;           // 64 x 68
    float* Kl = Kh + KT * APAD;
    float* Vh = Kl + KT * APAD;           // 64 x 68
    float* Vl = Vh + KT * APAD;
    float* Ph = Vl + KT * APAD;           // 128 x 68
    float* Pl = Ph + QT * APAD;
    float* redm = Pl + QT * APAD;         // 2 x 128
    float* reds = redm + 2 * QT;          // 2 x 128

    const int qi = (SEQ / QT - 1) - blockIdx.x;   // heavy tiles first (LPT)
    const int h  = blockIdx.y;
    const int b  = blockIdx.z;
    const int tid  = threadIdx.x;
    const int lane = tid & 31;
    const int w    = tid >> 5;
    const int grp  = lane >> 2;
    const int tig  = lane & 3;
    const int wm   = (w & 3) * 32;        // warp m offset (0..96)
    const int wn   = (w >> 2) * 32;       // warp n offset (0 or 32)
    const int warp_n = w >> 2;

    const float* Qg = g_q + ((size_t)(b * NH + h) * SEQ + (size_t)qi * QT) * DK;
    const float* Kg = g_k + (size_t)(b * NH + h) * SEQ * DK;
    const float* Vg = g_v + (size_t)(b * NH + h) * SEQ * DK;

    // ---- load Q tile (128 x 64), split hi/lo ----
    {
        const int r  = tid >> 1;
        const int c0 = (tid & 1) * 32;
#pragma unroll
        for (int p = 0; p < 8; p++) {
            float4 v = *(const float4*)(Qg + (size_t)r * DK + c0 + p * 4);
            float vv[4] = {v.x, v.y, v.z, v.w};
#pragma unroll
            for (int q = 0; q < 4; q++) {
                const float hf = __uint_as_float(f2tf32(vv[q]));
                Qh[r * APAD + c0 + p * 4 + q] = hf;
                Ql[r * APAD + c0 + p * 4 + q] = vv[q] - hf;
            }
        }
    }

    float m_i[2][2], l_i[2][2], o[2][4][4];
#pragma unroll
    for (int mi = 0; mi < 2; mi++)
#pragma unroll
        for (int hf = 0; hf < 2; hf++) { m_i[mi][hf] = -INFINITY; l_i[mi][hf] = 0.f; }
#pragma unroll
    for (int mi = 0; mi < 2; mi++)
#pragma unroll
        for (int ni = 0; ni < 4; ni++)
#pragma unroll
            for (int e = 0; e < 4; e++) o[mi][ni][e] = 0.f;

    const float scale = 0.125f;   // 1/sqrt(64)
    const int jmax = 2 * qi + 1;

    for (int j = 0; j <= jmax; j++) {
        __syncthreads();   // Q load done (iter 0) / prev PV readers done

        // ---- load K,V tiles (64 x 64), split hi/lo ----
        {
            const int r  = tid >> 2;
            const int c0 = (tid & 3) * 16;
#pragma unroll
            for (int p = 0; p < 4; p++) {
                float4 kv = *(const float4*)(Kg + (size_t)(j * KT + r) * DK + c0 + p * 4);
                float4 vv = *(const float4*)(Vg + (size_t)(j * KT + r) * DK + c0 + p * 4);
                float kk[4] = {kv.x, kv.y, kv.z, kv.w};
                float vf[4] = {vv.x, vv.y, vv.z, vv.w};
#pragma unroll
                for (int q = 0; q < 4; q++) {
                    const int c = c0 + p * 4 + q;
                    float hk = __uint_as_float(f2tf32(kk[q]));
                    Kh[r * APAD + c] = hk;
                    Kl[r * APAD + c] = kk[q] - hk;
                    float hv = __uint_as_float(f2tf32(vf[q]));
                    Vh[r * APAD + c] = hv;
                    Vl[r * APAD + c] = vf[q] - hv;
                }
            }
        }
        __syncthreads();

        // ---- S = Q K^T (split tf32) ----
        float s[2][4][4];
#pragma unroll
        for (int mi = 0; mi < 2; mi++)
#pragma unroll
            for (int ni = 0; ni < 4; ni++)
#pragma unroll
                for (int e = 0; e < 4; e++) s[mi][ni][e] = 0.f;

#pragma unroll
        for (int ks = 0; ks < 8; ks++) {
            const int kc = ks * 8 + tig;
            uint32_t ah[2][4], al[2][4];
#pragma unroll
            for (int mi = 0; mi < 2; mi++) {
                const int r0 = wm + mi * 16 + grp;
                ah[mi][0] = __float_as_uint(Qh[r0 * APAD + kc]);
                ah[mi][1] = __float_as_uint(Qh[(r0 + 8) * APAD + kc]);
                ah[mi][2] = __float_as_uint(Qh[r0 * APAD + kc + 4]);
                ah[mi][3] = __float_as_uint(Qh[(r0 + 8) * APAD + kc + 4]);
                al[mi][0] = __float_as_uint(Ql[r0 * APAD + kc]);
                al[mi][1] = __float_as_uint(Ql[(r0 + 8) * APAD + kc]);
                al[mi][2] = __float_as_uint(Ql[r0 * APAD + kc + 4]);
                al[mi][3] = __float_as_uint(Ql[(r0 + 8) * APAD + kc + 4]);
            }
#pragma unroll
            for (int ni = 0; ni < 4; ni++) {
                const int n0 = wn + ni * 8 + grp;
                uint32_t bh[2], bl[2];
                bh[0] = __float_as_uint(Kh[n0 * APAD + kc]);
                bh[1] = __float_as_uint(Kh[n0 * APAD + kc + 4]);
                bl[0] = __float_as_uint(Kl[n0 * APAD + kc]);
                bl[1] = __float_as_uint(Kl[n0 * APAD + kc + 4]);
#pragma unroll
                for (int mi = 0; mi < 2; mi++) {
                    mma_tf32(s[mi][ni], ah[mi], bh);
                    mma_tf32(s[mi][ni], ah[mi], bl);
                    mma_tf32(s[mi][ni], al[mi], bh);
                }
            }
        }

        // ---- scale + causal mask ----
        const bool need_mask = (j >= 2 * qi);
#pragma unroll
        for (int mi = 0; mi < 2; mi++)
#pragma unroll
            for (int ni = 0; ni < 4; ni++)
#pragma unroll
                for (int e = 0; e < 4; e++) {
                    float v = s[mi][ni][e] * scale;
                    if (need_mask) {
                        const int gr = qi * QT + wm + mi * 16 + grp + (e >> 1) * 8;
                        const int gc = j * KT + wn + ni * 8 + tig * 2 + (e & 1);
                        if (gc > gr) v = -INFINITY;
                    }
                    s[mi][ni][e] = v;
                }

        // ---- row max (quad shfl + cross-warp smem) ----
        float rmax[2][2];
#pragma unroll
        for (int mi = 0; mi < 2; mi++)
#pragma unroll
            for (int hf = 0; hf < 2; hf++) {
                float rm = -INFINITY;
#pragma unroll
                for (int ni = 0; ni < 4; ni++)
                    rm = fmaxf(rm, fmaxf(s[mi][ni][hf * 2], s[mi][ni][hf * 2 + 1]));
                rm = fmaxf(rm, __shfl_xor_sync(0xffffffffu, rm, 1));
                rm = fmaxf(rm, __shfl_xor_sync(0xffffffffu, rm, 2));
                rmax[mi][hf] = rm;
                if (tig == 0)
                    redm[warp_n * QT + wm + mi * 16 + grp + hf * 8] = rm;
            }
        __syncthreads();

        // ---- combine max, exp, local sums, P hi/lo write ----
        float alpha_s[2][2];
#pragma unroll
        for (int mi = 0; mi < 2; mi++)
#pragma unroll
            for (int hf = 0; hf < 2; hf++) {
                const int rl = wm + mi * 16 + grp + hf * 8;
                const float nm = fmaxf(m_i[mi][hf], fmaxf(redm[rl], redm[QT + rl]));
                const float alpha = __expf(m_i[mi][hf] - nm);
                m_i[mi][hf] = nm;
                alpha_s[mi][hf] = alpha;
                float rs = 0.f;
#pragma unroll
                for (int ni = 0; ni < 4; ni++) {
                    float p0 = __expf(s[mi][ni][hf * 2 + 0] - nm);
                    float p1 = __expf(s[mi][ni][hf * 2 + 1] - nm);
                    s[mi][ni][hf * 2 + 0] = p0;
                    s[mi][ni][hf * 2 + 1] = p1;
                    rs += p0 + p1;
                }
                rs += __shfl_xor_sync(0xffffffffu, rs, 1);
                rs += __shfl_xor_sync(0xffffffffu, rs, 2);
                if (tig == 0)
                    reds[warp_n * QT + rl] = rs;
                l_i[mi][hf] *= alpha;
#pragma unroll
                for (int ni = 0; ni < 4; ni++) {
                    o[mi][ni][hf * 2 + 0] *= alpha;
                    o[mi][ni][hf * 2 + 1] *= alpha;
                }
            }

        // P -> smem (hi/lo)
#pragma unroll
        for (int mi = 0; mi < 2; mi++)
#pragma unroll
            for (int ni = 0; ni < 4; ni++)
#pragma unroll
                for (int hf = 0; hf < 2; hf++) {
                    const int row = wm + mi * 16 + grp + hf * 8;
                    const int col = wn + ni * 8 + tig * 2;
                    const float p0 = s[mi][ni][hf * 2 + 0];
                    const float p1 = s[mi][ni][hf * 2 + 1];
                    const float h0 = __uint_as_float(f2tf32(p0));
                    const float h1 = __uint_as_float(f2tf32(p1));
                    *(float2*)&Ph[row * APAD + col] = make_float2(h0, h1);
                    *(float2*)&Pl[row * APAD + col] = make_float2(p0 - h0, p1 - h1);
                }
        __syncthreads();

#pragma unroll
        for (int mi = 0; mi < 2; mi++)
#pragma unroll
            for (int hf = 0; hf < 2; hf++) {
                const int rl = wm + mi * 16 + grp + hf * 8;
                l_i[mi][hf] += reds[rl] + reds[QT + rl];
            }

        // ---- O += P V (split tf32) ----
#pragma unroll
        for (int ks = 0; ks < 8; ks++) {
            const int kc = ks * 8 + tig;
            uint32_t ah[2][4], al[2][4];
#pragma unroll
            for (int mi = 0; mi < 2; mi++) {
                const int r0 = wm + mi * 16 + grp;
                ah[mi][0] = __float_as_uint(Ph[r0 * APAD + kc]);
                ah[mi][1] = __float_as_uint(Ph[(r0 + 8) * APAD + kc]);
                ah[mi][2] = __float_as_uint(Ph[r0 * APAD + kc + 4]);
                ah[mi][3] = __float_as_uint(Ph[(r0 + 8) * APAD + kc + 4]);
                al[mi][0] = __float_as_uint(Pl[r0 * APAD + kc]);
                al[mi][1] = __float_as_uint(Pl[(r0 + 8) * APAD + kc]);
                al[mi][2] = __float_as_uint(Pl[r0 * APAD + kc + 4]);
                al[mi][3] = __float_as_uint(Pl[(r0 + 8) * APAD + kc + 4]);
            }
#pragma unroll
            for (int ni = 0; ni < 4; ni++) {
                const int n0 = wn + ni * 8 + grp;
                uint32_t bh[2], bl[2];
                bh[0] = __float_as_uint(Vh[(ks * 8 + tig) * APAD + n0]);
                bh[1] = __float_as_uint(Vh[(ks * 8 + tig + 4) * APAD + n0]);
                bl[0] = __float_as_uint(Vl[(ks * 8 + tig) * APAD + n0]);
                bl[1] = __float_as_uint(Vl[(ks * 8 + tig + 4) * APAD + n0]);
#pragma unroll
                for (int mi = 0; mi < 2; mi++) {
                    mma_tf32(o[mi][ni], ah[mi], bh);
                    mma_tf32(o[mi][ni], ah[mi], bl);
                    mma_tf32(o[mi][ni], al[mi], bh);
                }
            }
        }
    }

    // ---- epilogue: normalize, write (B, S, D) layout ----
#pragma unroll
    for (int mi = 0; mi < 2; mi++)
#pragma unroll
        for (int hf = 0; hf < 2; hf++) {
            const float inv = 1.f / l_i[mi][hf];
            const int srow = qi * QT + wm + mi * 16 + grp + hf * 8;
#pragma unroll
            for (int ni = 0; ni < 4; ni++) {
                const int col = h * DK + wn + ni * 8 + tig * 2;
                float2 v = make_float2(o[mi][ni][hf * 2 + 0] * inv,
                                       o[mi][ni][hf * 2 + 1] * inv);
                *(float2*)&g_attn[((size_t)(b * SEQ) + srow) * DM + col] = v;
            }
        }
}

// ---------------------------------------------------------------------------

extern "C" void kernel_launch(void* const* d_in, const int* in_sizes, int n_in,
                              void* d_out, int out_size)
{
    const float* x  = (const float*)d_in[0];
    const float* Wq = (const float*)d_in[1];
    const float* bq = (const float*)d_in[2];
    const float* Wk = (const float*)d_in[3];
    const float* bk = (const float*)d_in[4];
    const float* Wv = (const float*)d_in[5];
    const float* bv = (const float*)d_in[6];
    const float* Wo = (const float*)d_in[7];
    const float* bo = (const float*)d_in[8];
    float* out = (float*)d_out;

    float *qp, *kp, *vp, *ap;
    cudaGetSymbolAddress((void**)&qp, g_q);
    cudaGetSymbolAddress((void**)&kp, g_k);
    cudaGetSymbolAddress((void**)&vp, g_v);
    cudaGetSymbolAddress((void**)&ap, g_attn);

    const dim3 ggrid(DM / 128, MTOT / 128);
    const int gemm_smem = 4 * 32 * LDA * (int)sizeof(float);

    cudaFuncSetAttribute(gemm_tf32<true>,  cudaFuncAttributeMaxDynamicSharedMemorySize, gemm_smem);
    cudaFuncSetAttribute(gemm_tf32<false>, cudaFuncAttributeMaxDynamicSharedMemorySize, gemm_smem);

    gemm_tf32<true><<<ggrid, 256, gemm_smem>>>(x, Wq, bq, qp);
    gemm_tf32<true><<<ggrid, 256, gemm_smem>>>(x, Wk, bk, kp);
    gemm_tf32<true><<<ggrid, 256, gemm_smem>>>(x, Wv, bv, vp);

    // attn smem: Q(2) + K(2) + V(2) + P(2) tiles + 2 reduce buffers
    const int attn_smem = (2 * QT * APAD + 4 * KT * APAD + 2 * QT * APAD + 4 * QT)
                          * (int)sizeof(float);   // 210,944 B
    cudaFuncSetAttribute(attn_mma, cudaFuncAttributeMaxDynamicSharedMemorySize,
                         attn_smem);
    attn_mma<<<dim3(SEQ / QT, NH, BATCH), 256, attn_smem>>>();

    gemm_tf32<false><<<ggrid, 256, gemm_smem>>>(ap, Wo, bo, out);
}

// round 10
// speedup vs baseline: 1.0024x; 1.0003x over previous
#include <cuda_runtime.h>
#include <math.h>
#include <stdint.h>

#define DM   768
#define NH   12
#define DK   64
#define BATCH 4
#define SEQ  2048
#define MTOT (BATCH*SEQ)   // 8192

// Scratch (device globals: allocation-free).
__device__ float g_q[(size_t)MTOT*DM];
__device__ float g_k[(size_t)MTOT*DM];
__device__ float g_v[(size_t)MTOT*DM];
__device__ float g_attn[(size_t)MTOT*DM];

// ---------------------------------------------------------------------------
// tf32 helpers
// ---------------------------------------------------------------------------
__device__ __forceinline__ uint32_t f2tf32(float x) {
    uint32_t r;
    asm("cvt.rna.tf32.f32 %0, %1;" : "=r"(r) : "f"(x));
    return r;
}

__device__ __forceinline__ void mma_tf32(float (&d)[4], const uint32_t (&a)[4],
                                         const uint32_t (&b)[2]) {
    asm volatile(
        "mma.sync.aligned.m16n8k8.row.col.f32.tf32.tf32.f32 "
        "{%0,%1,%2,%3}, {%4,%5,%6,%7}, {%8,%9}, {%0,%1,%2,%3};"
        : "+f"(d[0]), "+f"(d[1]), "+f"(d[2]), "+f"(d[3])
        : "r"(a[0]), "r"(a[1]), "r"(a[2]), "r"(a[3]), "r"(b[0]), "r"(b[1]));
}

// ---------------------------------------------------------------------------
// Split-precision tf32 GEMM: C = A(M x 768) @ W(768 x 768) + bias.
// (unchanged from R4)
// ---------------------------------------------------------------------------
#define LDA 136

template<bool HEAD_SPLIT>
__global__ __launch_bounds__(256)
void gemm_tf32(const float* __restrict__ A, const float* __restrict__ W,
               const float* __restrict__ bias, float* __restrict__ C)
{
    const int BM = 128, BN = 128, BK = 32;
    extern __shared__ float sm[];
    float* Ah = sm;
    float* Al = Ah + BK * LDA;
    float* Bh = Al + BK * LDA;
    float* Bl = Bh + BK * LDA;

    const int bm = blockIdx.y * BM;
    const int bn = blockIdx.x * BN;
    const int tid  = threadIdx.x;
    const int lane = tid & 31;
    const int w    = tid >> 5;
    const int grp  = lane >> 2;
    const int tig  = lane & 3;
    const int wm   = (w & 1) * 64;
    const int wn   = (w >> 1) * 32;

    float acc[4][4][4];
#pragma unroll
    for (int mi = 0; mi < 4; mi++)
#pragma unroll
        for (int ni = 0; ni < 4; ni++)
#pragma unroll
            for (int e = 0; e < 4; e++) acc[mi][ni][e] = 0.f;

    const int ar = tid >> 1;
    const int ac = (tid & 1) * 16;
    const int br = tid >> 3;
    const int bc = (tid & 7) * 16;

    for (int k0 = 0; k0 < DM; k0 += BK) {
#pragma unroll
        for (int p = 0; p < 4; p++) {
            float4 v = *(const float4*)(A + (size_t)(bm + ar) * DM + k0 + ac + p * 4);
            float vv[4] = {v.x, v.y, v.z, v.w};
#pragma unroll
            for (int q = 0; q < 4; q++) {
                const int k = ac + p * 4 + q;
                const float hf = __uint_as_float(f2tf32(vv[q]));
                Ah[k * LDA + ar] = hf;
                Al[k * LDA + ar] = vv[q] - hf;
            }
        }
#pragma unroll
        for (int p = 0; p < 4; p++) {
            float4 v = *(const float4*)(W + (size_t)(k0 + br) * DM + bn + bc + p * 4);
            float vv[4] = {v.x, v.y, v.z, v.w};
#pragma unroll
            for (int q = 0; q < 4; q++) {
                const float hf = __uint_as_float(f2tf32(vv[q]));
                Bh[br * LDA + bc + p * 4 + q] = hf;
                Bl[br * LDA + bc + p * 4 + q] = vv[q] - hf;
            }
        }
        __syncthreads();

#pragma unroll
        for (int ks = 0; ks < BK; ks += 8) {
            uint32_t a_h[4][4], a_l[4][4], b_h[4][2], b_l[4][2];
#pragma unroll
            for (int mi = 0; mi < 4; mi++) {
                const int m0 = wm + mi * 16 + grp;
                const int r0 = (ks + tig) * LDA;
                const int r4 = (ks + tig + 4) * LDA;
                a_h[mi][0] = __float_as_uint(Ah[r0 + m0]);
                a_h[mi][1] = __float_as_uint(Ah[r0 + m0 + 8]);
                a_h[mi][2] = __float_as_uint(Ah[r4 + m0]);
                a_h[mi][3] = __float_as_uint(Ah[r4 + m0 + 8]);
                a_l[mi][0] = __float_as_uint(Al[r0 + m0]);
                a_l[mi][1] = __float_as_uint(Al[r0 + m0 + 8]);
                a_l[mi][2] = __float_as_uint(Al[r4 + m0]);
                a_l[mi][3] = __float_as_uint(Al[r4 + m0 + 8]);
            }
#pragma unroll
            for (int ni = 0; ni < 4; ni++) {
                const int n0 = wn + ni * 8 + grp;
                b_h[ni][0] = __float_as_uint(Bh[(ks + tig) * LDA + n0]);
                b_h[ni][1] = __float_as_uint(Bh[(ks + tig + 4) * LDA + n0]);
                b_l[ni][0] = __float_as_uint(Bl[(ks + tig) * LDA + n0]);
                b_l[ni][1] = __float_as_uint(Bl[(ks + tig + 4) * LDA + n0]);
            }
#pragma unroll
            for (int mi = 0; mi < 4; mi++)
#pragma unroll
                for (int ni = 0; ni < 4; ni++) {
                    mma_tf32(acc[mi][ni], a_h[mi], b_h[ni]);
                    mma_tf32(acc[mi][ni], a_h[mi], b_l[ni]);
                    mma_tf32(acc[mi][ni], a_l[mi], b_h[ni]);
                }
        }
        __syncthreads();
    }

#pragma unroll
    for (int mi = 0; mi < 4; mi++) {
#pragma unroll
        for (int ni = 0; ni < 4; ni++) {
#pragma unroll
            for (int e = 0; e < 4; e++) {
                const int m = bm + wm + mi * 16 + grp + (e >> 1) * 8;
                const int n = bn + wn + ni * 8 + tig * 2 + (e & 1);
                const float v = acc[mi][ni][e] + bias[n];
                if (HEAD_SPLIT) {
                    const int bb = m >> 11, ss = m & (SEQ - 1);
                    const int hh = n >> 6,  dd = n & (DK - 1);
                    C[((size_t)(bb * NH + hh) * SEQ + ss) * DK + dd] = v;
                } else {
                    C[(size_t)m * DM + n] = v;
                }
            }
        }
    }
}

// ---------------------------------------------------------------------------
// Tensor-core flash attention (causal, online softmax, split-tf32 MMA).
// Block = (b, h, 128-row q tile); 8 warps as 4(m) x 2(n); 32x32 warp tiles.
// ---------------------------------------------------------------------------
#define QT   128
#define KT   64
#define APAD 68

__global__ __launch_bounds__(256)
void attn_mma()
{
    extern __shared__ float sm[];
    float* Qh = sm;                       // 128 x 68
    float* Ql = Qh + QT * APAD;
    float* Kh = Ql + QT * APAD;           // 64 x 68
    float* Kl = Kh + KT * APAD;
    float* Vh = Kl + KT * APAD;           // 64 x 68
    float* Vl = Vh + KT * APAD;
    float* Ph = Vl + KT * APAD;           // 128 x 68
    float* Pl = Ph + QT * APAD;
    float* redm = Pl + QT * APAD;         // 2 x 128
    float* reds = redm + 2 * QT;          // 2 x 128

    const int qi = (SEQ / QT - 1) - blockIdx.x;   // heavy tiles first (LPT)
    const int h  = blockIdx.y;
    const int b  = blockIdx.z;
    const int tid  = threadIdx.x;
    const int lane = tid & 31;
    const int w    = tid >> 5;
    const int grp  = lane >> 2;
    const int tig  = lane & 3;
    const int wm   = (w & 3) * 32;        // warp m offset (0..96)
    const int wn   = (w >> 2) * 32;       // warp n offset (0 or 32)
    const int warp_n = w >> 2;

    const float* Qg = g_q + ((size_t)(b * NH + h) * SEQ + (size_t)qi * QT) * DK;
    const float* Kg = g_k + (size_t)(b * NH + h) * SEQ * DK;
    const float* Vg = g_v + (size_t)(b * NH + h) * SEQ * DK;

    // ---- load Q tile (128 x 64), split hi/lo ----
    {
        const int r  = tid >> 1;
        const int c0 = (tid & 1) * 32;
#pragma unroll
        for (int p = 0; p < 8; p++) {
            float4 v = *(const float4*)(Qg + (size_t)r * DK + c0 + p * 4);
            float vv[4] = {v.x, v.y, v.z, v.w};
#pragma unroll
            for (int q = 0; q < 4; q++) {
                const float hf = __uint_as_float(f2tf32(vv[q]));
                Qh[r * APAD + c0 + p * 4 + q] = hf;
                Ql[r * APAD + c0 + p * 4 + q] = vv[q] - hf;
            }
        }
    }

    float m_i[2][2], l_i[2][2], o[2][4][4];
#pragma unroll
    for (int mi = 0; mi < 2; mi++)
#pragma unroll
        for (int hf = 0; hf < 2; hf++) { m_i[mi][hf] = -INFINITY; l_i[mi][hf] = 0.f; }
#pragma unroll
    for (int mi = 0; mi < 2; mi++)
#pragma unroll
        for (int ni = 0; ni < 4; ni++)
#pragma unroll
            for (int e = 0; e < 4; e++) o[mi][ni][e] = 0.f;

    const float scale = 0.125f;   // 1/sqrt(64)
    const int jmax = 2 * qi + 1;

    for (int j = 0; j <= jmax; j++) {
        __syncthreads();   // Q load done (iter 0) / prev PV readers done

        // ---- load K,V tiles (64 x 64), split hi/lo ----
        {
            const int r  = tid >> 2;
            const int c0 = (tid & 3) * 16;
#pragma unroll
            for (int p = 0; p < 4; p++) {
                float4 kv = *(const float4*)(Kg + (size_t)(j * KT + r) * DK + c0 + p * 4);
                float4 vv = *(const float4*)(Vg + (size_t)(j * KT + r) * DK + c0 + p * 4);
                float kk[4] = {kv.x, kv.y, kv.z, kv.w};
                float vf[4] = {vv.x, vv.y, vv.z, vv.w};
#pragma unroll
                for (int q = 0; q < 4; q++) {
                    const int c = c0 + p * 4 + q;
                    float hk = __uint_as_float(f2tf32(kk[q]));
                    Kh[r * APAD + c] = hk;
                    Kl[r * APAD + c] = kk[q] - hk;
                    float hv = __uint_as_float(f2tf32(vf[q]));
                    Vh[r * APAD + c] = hv;
                    Vl[r * APAD + c] = vf[q] - hv;
                }
            }
        }
        __syncthreads();

        // ---- S = Q K^T (split tf32) ----
        float s[2][4][4];
#pragma unroll
        for (int mi = 0; mi < 2; mi++)
#pragma unroll
            for (int ni = 0; ni < 4; ni++)
#pragma unroll
                for (int e = 0; e < 4; e++) s[mi][ni][e] = 0.f;

#pragma unroll
        for (int ks = 0; ks < 8; ks++) {
            const int kc = ks * 8 + tig;
            uint32_t ah[2][4], al[2][4];
#pragma unroll
            for (int mi = 0; mi < 2; mi++) {
                const int r0 = wm + mi * 16 + grp;
                ah[mi][0] = __float_as_uint(Qh[r0 * APAD + kc]);
                ah[mi][1] = __float_as_uint(Qh[(r0 + 8) * APAD + kc]);
                ah[mi][2] = __float_as_uint(Qh[r0 * APAD + kc + 4]);
                ah[mi][3] = __float_as_uint(Qh[(r0 + 8) * APAD + kc + 4]);
                al[mi][0] = __float_as_uint(Ql[r0 * APAD + kc]);
                al[mi][1] = __float_as_uint(Ql[(r0 + 8) * APAD + kc]);
                al[mi][2] = __float_as_uint(Ql[r0 * APAD + kc + 4]);
                al[mi][3] = __float_as_uint(Ql[(r0 + 8) * APAD + kc + 4]);
            }
#pragma unroll
            for (int ni = 0; ni < 4; ni++) {
                const int n0 = wn + ni * 8 + grp;
                uint32_t bh[2], bl[2];
                bh[0] = __float_as_uint(Kh[n0 * APAD + kc]);
                bh[1] = __float_as_uint(Kh[n0 * APAD + kc + 4]);
                bl[0] = __float_as_uint(Kl[n0 * APAD + kc]);
                bl[1] = __float_as_uint(Kl[n0 * APAD + kc + 4]);
#pragma unroll
                for (int mi = 0; mi < 2; mi++) {
                    mma_tf32(s[mi][ni], ah[mi], bh);
                    mma_tf32(s[mi][ni], ah[mi], bl);
                    mma_tf32(s[mi][ni], al[mi], bh);
                }
            }
        }

        // ---- scale + causal mask ----
        const bool need_mask = (j >= 2 * qi);
#pragma unroll
        for (int mi = 0; mi < 2; mi++)
#pragma unroll
            for (int ni = 0; ni < 4; ni++)
#pragma unroll
                for (int e = 0; e < 4; e++) {
                    float v = s[mi][ni][e] * scale;
                    if (need_mask) {
                        const int gr = qi * QT + wm + mi * 16 + grp + (e >> 1) * 8;
                        const int gc = j * KT + wn + ni * 8 + tig * 2 + (e & 1);
                        if (gc > gr) v = -INFINITY;
                    }
                    s[mi][ni][e] = v;
                }

        // ---- row max (quad shfl + cross-warp smem) ----
        float rmax[2][2];
#pragma unroll
        for (int mi = 0; mi < 2; mi++)
#pragma unroll
            for (int hf = 0; hf < 2; hf++) {
                float rm = -INFINITY;
#pragma unroll
                for (int ni = 0; ni < 4; ni++)
                    rm = fmaxf(rm, fmaxf(s[mi][ni][hf * 2], s[mi][ni][hf * 2 + 1]));
                rm = fmaxf(rm, __shfl_xor_sync(0xffffffffu, rm, 1));
                rm = fmaxf(rm, __shfl_xor_sync(0xffffffffu, rm, 2));
                rmax[mi][hf] = rm;
                if (tig == 0)
                    redm[warp_n * QT + wm + mi * 16 + grp + hf * 8] = rm;
            }
        __syncthreads();

        // ---- combine max, exp, local sums, P hi/lo write ----
        float alpha_s[2][2];
#pragma unroll
        for (int mi = 0; mi < 2; mi++)
#pragma unroll
            for (int hf = 0; hf < 2; hf++) {
                const int rl = wm + mi * 16 + grp + hf * 8;
                const float nm = fmaxf(m_i[mi][hf], fmaxf(redm[rl], redm[QT + rl]));
                const float alpha = __expf(m_i[mi][hf] - nm);
                m_i[mi][hf] = nm;
                alpha_s[mi][hf] = alpha;
                float rs = 0.f;
#pragma unroll
                for (int ni = 0; ni < 4; ni++) {
                    float p0 = __expf(s[mi][ni][hf * 2 + 0] - nm);
                    float p1 = __expf(s[mi][ni][hf * 2 + 1] - nm);
                    s[mi][ni][hf * 2 + 0] = p0;
                    s[mi][ni][hf * 2 + 1] = p1;
                    rs += p0 + p1;
                }
                rs += __shfl_xor_sync(0xffffffffu, rs, 1);
                rs += __shfl_xor_sync(0xffffffffu, rs, 2);
                if (tig == 0)
                    reds[warp_n * QT + rl] = rs;
                l_i[mi][hf] *= alpha;
#pragma unroll
                for (int ni = 0; ni < 4; ni++) {
                    o[mi][ni][hf * 2 + 0] *= alpha;
                    o[mi][ni][hf * 2 + 1] *= alpha;
                }
            }

        // P -> smem (hi/lo)
#pragma unroll
        for (int mi = 0; mi < 2; mi++)
#pragma unroll
            for (int ni = 0; ni < 4; ni++)
#pragma unroll
                for (int hf = 0; hf < 2; hf++) {
                    const int row = wm + mi * 16 + grp + hf * 8;
                    const int col = wn + ni * 8 + tig * 2;
                    const float p0 = s[mi][ni][hf * 2 + 0];
                    const float p1 = s[mi][ni][hf * 2 + 1];
                    const float h0 = __uint_as_float(f2tf32(p0));
                    const float h1 = __uint_as_float(f2tf32(p1));
                    *(float2*)&Ph[row * APAD + col] = make_float2(h0, h1);
                    *(float2*)&Pl[row * APAD + col] = make_float2(p0 - h0, p1 - h1);
                }
        __syncthreads();

#pragma unroll
        for (int mi = 0; mi < 2; mi++)
#pragma unroll
            for (int hf = 0; hf < 2; hf++) {
                const int rl = wm + mi * 16 + grp + hf * 8;
                l_i[mi][hf] += reds[rl] + reds[QT + rl];
            }

        // ---- O += P V (split tf32) ----
#pragma unroll
        for (int ks = 0; ks < 8; ks++) {
            const int kc = ks * 8 + tig;
            uint32_t ah[2][4], al[2][4];
#pragma unroll
            for (int mi = 0; mi < 2; mi++) {
                const int r0 = wm + mi * 16 + grp;
                ah[mi][0] = __float_as_uint(Ph[r0 * APAD + kc]);
                ah[mi][1] = __float_as_uint(Ph[(r0 + 8) * APAD + kc]);
                ah[mi][2] = __float_as_uint(Ph[r0 * APAD + kc + 4]);
                ah[mi][3] = __float_as_uint(Ph[(r0 + 8) * APAD + kc + 4]);
                al[mi][0] = __float_as_uint(Pl[r0 * APAD + kc]);
                al[mi][1] = __float_as_uint(Pl[(r0 + 8) * APAD + kc]);
                al[mi][2] = __float_as_uint(Pl[r0 * APAD + kc + 4]);
                al[mi][3] = __float_as_uint(Pl[(r0 + 8) * APAD + kc + 4]);
            }
#pragma unroll
            for (int ni = 0; ni < 4; ni++) {
                const int n0 = wn + ni * 8 + grp;
                uint32_t bh[2], bl[2];
                bh[0] = __float_as_uint(Vh[(ks * 8 + tig) * APAD + n0]);
                bh[1] = __float_as_uint(Vh[(ks * 8 + tig + 4) * APAD + n0]);
                bl[0] = __float_as_uint(Vl[(ks * 8 + tig) * APAD + n0]);
                bl[1] = __float_as_uint(Vl[(ks * 8 + tig + 4) * APAD + n0]);
#pragma unroll
                for (int mi = 0; mi < 2; mi++) {
                    mma_tf32(o[mi][ni], ah[mi], bh);
                    mma_tf32(o[mi][ni], ah[mi], bl);
                    mma_tf32(o[mi][ni], al[mi], bh);
                }
            }
        }
    }

    // ---- epilogue: normalize, write (B, S, D) layout ----
#pragma unroll
    for (int mi = 0; mi < 2; mi++)
#pragma unroll
        for (int hf = 0; hf < 2; hf++) {
            const float inv = 1.f / l_i[mi][hf];
            const int srow = qi * QT + wm + mi * 16 + grp + hf * 8;
#pragma unroll
            for (int ni = 0; ni < 4; ni++) {
                const int col = h * DK + wn + ni * 8 + tig * 2;
                float2 v = make_float2(o[mi][ni][hf * 2 + 0] * inv,
                                       o[mi][ni][hf * 2 + 1] * inv);
                *(float2*)&g_attn[((size_t)(b * SEQ) + srow) * DM + col] = v;
            }
        }
}

// ---------------------------------------------------------------------------

extern "C" void kernel_launch(void* const* d_in, const int* in_sizes, int n_in,
                              void* d_out, int out_size)
{
    const float* x  = (const float*)d_in[0];
    const float* Wq = (const float*)d_in[1];
    const float* bq = (const float*)d_in[2];
    const float* Wk = (const float*)d_in[3];
    const float* bk = (const float*)d_in[4];
    const float* Wv = (const float*)d_in[5];
    const float* bv = (const float*)d_in[6];
    const float* Wo = (const float*)d_in[7];
    const float* bo = (const float*)d_in[8];
    float* out = (float*)d_out;

    float *qp, *kp, *vp, *ap;
    cudaGetSymbolAddress((void**)&qp, g_q);
    cudaGetSymbolAddress((void**)&kp, g_k);
    cudaGetSymbolAddress((void**)&vp, g_v);
    cudaGetSymbolAddress((void**)&ap, g_attn);

    const dim3 ggrid(DM / 128, MTOT / 128);
    const int gemm_smem = 4 * 32 * LDA * (int)sizeof(float);

    cudaFuncSetAttribute(gemm_tf32<true>,  cudaFuncAttributeMaxDynamicSharedMemorySize, gemm_smem);
    cudaFuncSetAttribute(gemm_tf32<false>, cudaFuncAttributeMaxDynamicSharedMemorySize, gemm_smem);

    gemm_tf32<true><<<ggrid, 256, gemm_smem>>>(x, Wq, bq, qp);
    gemm_tf32<true><<<ggrid, 256, gemm_smem>>>(x, Wk, bk, kp);
    gemm_tf32<true><<<ggrid, 256, gemm_smem>>>(x, Wv, bv, vp);

    // attn smem: Q(2) + K(2) + V(2) + P(2) tiles + 2 reduce buffers
    const int attn_smem = (2 * QT * APAD + 4 * KT * APAD + 2 * QT * APAD + 4 * QT)
                          * (int)sizeof(float);   // 210,944 B
    cudaFuncSetAttribute(attn_mma, cudaFuncAttributeMaxDynamicSharedMemorySize,
                         attn_smem);
    attn_mma<<<dim3(SEQ / QT, NH, BATCH), 256, attn_smem>>>();

    gemm_tf32<false><<<ggrid, 256, gemm_smem>>>(ap, Wo, bo, out);
}

// round 12
// speedup vs baseline: 1.0033x; 1.0009x over previous
#include <cuda_runtime.h>
#include <math.h>
#include <stdint.h>

#define DM   768
#define NH   12
#define DK   64
#define BATCH 4
#define SEQ  2048
#define MTOT (BATCH*SEQ)   // 8192

// Scratch (device globals: allocation-free).
__device__ float g_q[(size_t)MTOT*DM];
__device__ float g_k[(size_t)MTOT*DM];
__device__ float g_v[(size_t)MTOT*DM];
__device__ float g_attn[(size_t)MTOT*DM];

// ---------------------------------------------------------------------------
// tf32 helpers
// ---------------------------------------------------------------------------
__device__ __forceinline__ uint32_t f2tf32(float x) {
    uint32_t r;
    asm("cvt.rna.tf32.f32 %0, %1;" : "=r"(r) : "f"(x));
    return r;
}

__device__ __forceinline__ void mma_tf32(float (&d)[4], const uint32_t (&a)[4],
                                         const uint32_t (&b)[2]) {
    asm volatile(
        "mma.sync.aligned.m16n8k8.row.col.f32.tf32.tf32.f32 "
        "{%0,%1,%2,%3}, {%4,%5,%6,%7}, {%8,%9}, {%0,%1,%2,%3};"
        : "+f"(d[0]), "+f"(d[1]), "+f"(d[2]), "+f"(d[3])
        : "r"(a[0]), "r"(a[1]), "r"(a[2]), "r"(a[3]), "r"(b[0]), "r"(b[1]));
}

// ---------------------------------------------------------------------------
// Split-precision tf32 GEMM: C = A(M x 768) @ W(768 x 768) + bias.
// (unchanged from R4)
// ---------------------------------------------------------------------------
#define LDA 136

template<bool HEAD_SPLIT>
__global__ __launch_bounds__(256)
void gemm_tf32(const float* __restrict__ A, const float* __restrict__ W,
               const float* __restrict__ bias, float* __restrict__ C)
{
    const int BM = 128, BN = 128, BK = 32;
    extern __shared__ float sm[];
    float* Ah = sm;
    float* Al = Ah + BK * LDA;
    float* Bh = Al + BK * LDA;
    float* Bl = Bh + BK * LDA;

    const int bm = blockIdx.y * BM;
    const int bn = blockIdx.x * BN;
    const int tid  = threadIdx.x;
    const int lane = tid & 31;
    const int w    = tid >> 5;
    const int grp  = lane >> 2;
    const int tig  = lane & 3;
    const int wm   = (w & 1) * 64;
    const int wn   = (w >> 1) * 32;

    float acc[4][4][4];
#pragma unroll
    for (int mi = 0; mi < 4; mi++)
#pragma unroll
        for (int ni = 0; ni < 4; ni++)
#pragma unroll
            for (int e = 0; e < 4; e++) acc[mi][ni][e] = 0.f;

    const int ar = tid >> 1;
    const int ac = (tid & 1) * 16;
    const int br = tid >> 3;
    const int bc = (tid & 7) * 16;

    for (int k0 = 0; k0 < DM; k0 += BK) {
#pragma unroll
        for (int p = 0; p < 4; p++) {
            float4 v = *(const float4*)(A + (size_t)(bm + ar) * DM + k0 + ac + p * 4);
            float vv[4] = {v.x, v.y, v.z, v.w};
#pragma unroll
            for (int q = 0; q < 4; q++) {
                const int k = ac + p * 4 + q;
                const float hf = __uint_as_float(f2tf32(vv[q]));
                Ah[k * LDA + ar] = hf;
                Al[k * LDA + ar] = vv[q] - hf;
            }
        }
#pragma unroll
        for (int p = 0; p < 4; p++) {
            float4 v = *(const float4*)(W + (size_t)(k0 + br) * DM + bn + bc + p * 4);
            float vv[4] = {v.x, v.y, v.z, v.w};
#pragma unroll
            for (int q = 0; q < 4; q++) {
                const float hf = __uint_as_float(f2tf32(vv[q]));
                Bh[br * LDA + bc + p * 4 + q] = hf;
                Bl[br * LDA + bc + p * 4 + q] = vv[q] - hf;
            }
        }
        __syncthreads();

#pragma unroll
        for (int ks = 0; ks < BK; ks += 8) {
            uint32_t a_h[4][4], a_l[4][4], b_h[4][2], b_l[4][2];
#pragma unroll
            for (int mi = 0; mi < 4; mi++) {
                const int m0 = wm + mi * 16 + grp;
                const int r0 = (ks + tig) * LDA;
                const int r4 = (ks + tig + 4) * LDA;
                a_h[mi][0] = __float_as_uint(Ah[r0 + m0]);
                a_h[mi][1] = __float_as_uint(Ah[r0 + m0 + 8]);
                a_h[mi][2] = __float_as_uint(Ah[r4 + m0]);
                a_h[mi][3] = __float_as_uint(Ah[r4 + m0 + 8]);
                a_l[mi][0] = __float_as_uint(Al[r0 + m0]);
                a_l[mi][1] = __float_as_uint(Al[r0 + m0 + 8]);
                a_l[mi][2] = __float_as_uint(Al[r4 + m0]);
                a_l[mi][3] = __float_as_uint(Al[r4 + m0 + 8]);
            }
#pragma unroll
            for (int ni = 0; ni < 4; ni++) {
                const int n0 = wn + ni * 8 + grp;
                b_h[ni][0] = __float_as_uint(Bh[(ks + tig) * LDA + n0]);
                b_h[ni][1] = __float_as_uint(Bh[(ks + tig + 4) * LDA + n0]);
                b_l[ni][0] = __float_as_uint(Bl[(ks + tig) * LDA + n0]);
                b_l[ni][1] = __float_as_uint(Bl[(ks + tig + 4) * LDA + n0]);
            }
#pragma unroll
            for (int mi = 0; mi < 4; mi++)
#pragma unroll
                for (int ni = 0; ni < 4; ni++) {
                    mma_tf32(acc[mi][ni], a_h[mi], b_h[ni]);
                    mma_tf32(acc[mi][ni], a_h[mi], b_l[ni]);
                    mma_tf32(acc[mi][ni], a_l[mi], b_h[ni]);
                }
        }
        __syncthreads();
    }

#pragma unroll
    for (int mi = 0; mi < 4; mi++) {
#pragma unroll
        for (int ni = 0; ni < 4; ni++) {
#pragma unroll
            for (int e = 0; e < 4; e++) {
                const int m = bm + wm + mi * 16 + grp + (e >> 1) * 8;
                const int n = bn + wn + ni * 8 + tig * 2 + (e & 1);
                const float v = acc[mi][ni][e] + bias[n];
                if (HEAD_SPLIT) {
                    const int bb = m >> 11, ss = m & (SEQ - 1);
                    const int hh = n >> 6,  dd = n & (DK - 1);
                    C[((size_t)(bb * NH + hh) * SEQ + ss) * DK + dd] = v;
                } else {
                    C[(size_t)m * DM + n] = v;
                }
            }
        }
    }
}

// ---------------------------------------------------------------------------
// Tensor-core flash attention (causal, online softmax, split-tf32 MMA).
// Block = (b, h, 128-row q tile); 8 warps as 4(m) x 2(n); 32x32 warp tiles.
// ---------------------------------------------------------------------------
#define QT   128
#define KT   64
#define APAD 68

__global__ __launch_bounds__(256)
void attn_mma()
{
    extern __shared__ float sm[];
    float* Qh = sm;                       // 128 x 68
    float* Ql = Qh + QT * APAD;
    float* Kh = Ql + QT * APAD;           // 64 x 68
    float* Kl = Kh + KT * APAD;
    float* Vh = Kl + KT * APAD;           // 64 x 68
    float* Vl = Vh + KT * APAD;
    float* Ph = Vl + KT * APAD;           // 128 x 68
    float* Pl = Ph + QT * APAD;
    float* redm = Pl + QT * APAD;         // 2 x 128
    float* reds = redm + 2 * QT;          // 2 x 128

    const int qi = (SEQ / QT - 1) - blockIdx.x;   // heavy tiles first (LPT)
    const int h  = blockIdx.y;
    const int b  = blockIdx.z;
    const int tid  = threadIdx.x;
    const int lane = tid & 31;
    const int w    = tid >> 5;
    const int grp  = lane >> 2;
    const int tig  = lane & 3;
    const int wm   = (w & 3) * 32;        // warp m offset (0..96)
    const int wn   = (w >> 2) * 32;       // warp n offset (0 or 32)
    const int warp_n = w >> 2;

    const float* Qg = g_q + ((size_t)(b * NH + h) * SEQ + (size_t)qi * QT) * DK;
    const float* Kg = g_k + (size_t)(b * NH + h) * SEQ * DK;
    const float* Vg = g_v + (size_t)(b * NH + h) * SEQ * DK;

    // ---- load Q tile (128 x 64), split hi/lo ----
    {
        const int r  = tid >> 1;
        const int c0 = (tid & 1) * 32;
#pragma unroll
        for (int p = 0; p < 8; p++) {
            float4 v = *(const float4*)(Qg + (size_t)r * DK + c0 + p * 4);
            float vv[4] = {v.x, v.y, v.z, v.w};
#pragma unroll
            for (int q = 0; q < 4; q++) {
                const float hf = __uint_as_float(f2tf32(vv[q]));
                Qh[r * APAD + c0 + p * 4 + q] = hf;
                Ql[r * APAD + c0 + p * 4 + q] = vv[q] - hf;
            }
        }
    }

    float m_i[2][2], l_i[2][2], o[2][4][4];
#pragma unroll
    for (int mi = 0; mi < 2; mi++)
#pragma unroll
        for (int hf = 0; hf < 2; hf++) { m_i[mi][hf] = -INFINITY; l_i[mi][hf] = 0.f; }
#pragma unroll
    for (int mi = 0; mi < 2; mi++)
#pragma unroll
        for (int ni = 0; ni < 4; ni++)
#pragma unroll
            for (int e = 0; e < 4; e++) o[mi][ni][e] = 0.f;

    const float scale = 0.125f;   // 1/sqrt(64)
    const int jmax = 2 * qi + 1;

    for (int j = 0; j <= jmax; j++) {
        __syncthreads();   // Q load done (iter 0) / prev PV readers done

        // ---- load K,V tiles (64 x 64), split hi/lo ----
        {
            const int r  = tid >> 2;
            const int c0 = (tid & 3) * 16;
#pragma unroll
            for (int p = 0; p < 4; p++) {
                float4 kv = *(const float4*)(Kg + (size_t)(j * KT + r) * DK + c0 + p * 4);
                float4 vv = *(const float4*)(Vg + (size_t)(j * KT + r) * DK + c0 + p * 4);
                float kk[4] = {kv.x, kv.y, kv.z, kv.w};
                float vf[4] = {vv.x, vv.y, vv.z, vv.w};
#pragma unroll
                for (int q = 0; q < 4; q++) {
                    const int c = c0 + p * 4 + q;
                    float hk = __uint_as_float(f2tf32(kk[q]));
                    Kh[r * APAD + c] = hk;
                    Kl[r * APAD + c] = kk[q] - hk;
                    float hv = __uint_as_float(f2tf32(vf[q]));
                    Vh[r * APAD + c] = hv;
                    Vl[r * APAD + c] = vf[q] - hv;
                }
            }
        }
        __syncthreads();

        // ---- S = Q K^T (split tf32) ----
        float s[2][4][4];
#pragma unroll
        for (int mi = 0; mi < 2; mi++)
#pragma unroll
            for (int ni = 0; ni < 4; ni++)
#pragma unroll
                for (int e = 0; e < 4; e++) s[mi][ni][e] = 0.f;

#pragma unroll
        for (int ks = 0; ks < 8; ks++) {
            const int kc = ks * 8 + tig;
            uint32_t ah[2][4], al[2][4];
#pragma unroll
            for (int mi = 0; mi < 2; mi++) {
                const int r0 = wm + mi * 16 + grp;
                ah[mi][0] = __float_as_uint(Qh[r0 * APAD + kc]);
                ah[mi][1] = __float_as_uint(Qh[(r0 + 8) * APAD + kc]);
                ah[mi][2] = __float_as_uint(Qh[r0 * APAD + kc + 4]);
                ah[mi][3] = __float_as_uint(Qh[(r0 + 8) * APAD + kc + 4]);
                al[mi][0] = __float_as_uint(Ql[r0 * APAD + kc]);
                al[mi][1] = __float_as_uint(Ql[(r0 + 8) * APAD + kc]);
                al[mi][2] = __float_as_uint(Ql[r0 * APAD + kc + 4]);
                al[mi][3] = __float_as_uint(Ql[(r0 + 8) * APAD + kc + 4]);
            }
#pragma unroll
            for (int ni = 0; ni < 4; ni++) {
                const int n0 = wn + ni * 8 + grp;
                uint32_t bh[2], bl[2];
                bh[0] = __float_as_uint(Kh[n0 * APAD + kc]);
                bh[1] = __float_as_uint(Kh[n0 * APAD + kc + 4]);
                bl[0] = __float_as_uint(Kl[n0 * APAD + kc]);
                bl[1] = __float_as_uint(Kl[n0 * APAD + kc + 4]);
#pragma unroll
                for (int mi = 0; mi < 2; mi++) {
                    mma_tf32(s[mi][ni], ah[mi], bh);
                    mma_tf32(s[mi][ni], ah[mi], bl);
                    mma_tf32(s[mi][ni], al[mi], bh);
                }
            }
        }

        // ---- scale + causal mask ----
        const bool need_mask = (j >= 2 * qi);
#pragma unroll
        for (int mi = 0; mi < 2; mi++)
#pragma unroll
            for (int ni = 0; ni < 4; ni++)
#pragma unroll
                for (int e = 0; e < 4; e++) {
                    float v = s[mi][ni][e] * scale;
                    if (need_mask) {
                        const int gr = qi * QT + wm + mi * 16 + grp + (e >> 1) * 8;
                        const int gc = j * KT + wn + ni * 8 + tig * 2 + (e & 1);
                        if (gc > gr) v = -INFINITY;
                    }
                    s[mi][ni][e] = v;
                }

        // ---- row max (quad shfl + cross-warp smem) ----
        float rmax[2][2];
#pragma unroll
        for (int mi = 0; mi < 2; mi++)
#pragma unroll
            for (int hf = 0; hf < 2; hf++) {
                float rm = -INFINITY;
#pragma unroll
                for (int ni = 0; ni < 4; ni++)
                    rm = fmaxf(rm, fmaxf(s[mi][ni][hf * 2], s[mi][ni][hf * 2 + 1]));
                rm = fmaxf(rm, __shfl_xor_sync(0xffffffffu, rm, 1));
                rm = fmaxf(rm, __shfl_xor_sync(0xffffffffu, rm, 2));
                rmax[mi][hf] = rm;
                if (tig == 0)
                    redm[warp_n * QT + wm + mi * 16 + grp + hf * 8] = rm;
            }
        __syncthreads();

        // ---- combine max, exp, local sums, P hi/lo write ----
        float alpha_s[2][2];
#pragma unroll
        for (int mi = 0; mi < 2; mi++)
#pragma unroll
            for (int hf = 0; hf < 2; hf++) {
                const int rl = wm + mi * 16 + grp + hf * 8;
                const float nm = fmaxf(m_i[mi][hf], fmaxf(redm[rl], redm[QT + rl]));
                const float alpha = __expf(m_i[mi][hf] - nm);
                m_i[mi][hf] = nm;
                alpha_s[mi][hf] = alpha;
                float rs = 0.f;
#pragma unroll
                for (int ni = 0; ni < 4; ni++) {
                    float p0 = __expf(s[mi][ni][hf * 2 + 0] - nm);
                    float p1 = __expf(s[mi][ni][hf * 2 + 1] - nm);
                    s[mi][ni][hf * 2 + 0] = p0;
                    s[mi][ni][hf * 2 + 1] = p1;
                    rs += p0 + p1;
                }
                rs += __shfl_xor_sync(0xffffffffu, rs, 1);
                rs += __shfl_xor_sync(0xffffffffu, rs, 2);
                if (tig == 0)
                    reds[warp_n * QT + rl] = rs;
                l_i[mi][hf] *= alpha;
#pragma unroll
                for (int ni = 0; ni < 4; ni++) {
                    o[mi][ni][hf * 2 + 0] *= alpha;
                    o[mi][ni][hf * 2 + 1] *= alpha;
                }
            }

        // P -> smem (hi/lo)
#pragma unroll
        for (int mi = 0; mi < 2; mi++)
#pragma unroll
            for (int ni = 0; ni < 4; ni++)
#pragma unroll
                for (int hf = 0; hf < 2; hf++) {
                    const int row = wm + mi * 16 + grp + hf * 8;
                    const int col = wn + ni * 8 + tig * 2;
                    const float p0 = s[mi][ni][hf * 2 + 0];
                    const float p1 = s[mi][ni][hf * 2 + 1];
                    const float h0 = __uint_as_float(f2tf32(p0));
                    const float h1 = __uint_as_float(f2tf32(p1));
                    *(float2*)&Ph[row * APAD + col] = make_float2(h0, h1);
                    *(float2*)&Pl[row * APAD + col] = make_float2(p0 - h0, p1 - h1);
                }
        __syncthreads();

#pragma unroll
        for (int mi = 0; mi < 2; mi++)
#pragma unroll
            for (int hf = 0; hf < 2; hf++) {
                const int rl = wm + mi * 16 + grp + hf * 8;
                l_i[mi][hf] += reds[rl] + reds[QT + rl];
            }

        // ---- O += P V (split tf32) ----
#pragma unroll
        for (int ks = 0; ks < 8; ks++) {
            const int kc = ks * 8 + tig;
            uint32_t ah[2][4], al[2][4];
#pragma unroll
            for (int mi = 0; mi < 2; mi++) {
                const int r0 = wm + mi * 16 + grp;
                ah[mi][0] = __float_as_uint(Ph[r0 * APAD + kc]);
                ah[mi][1] = __float_as_uint(Ph[(r0 + 8) * APAD + kc]);
                ah[mi][2] = __float_as_uint(Ph[r0 * APAD + kc + 4]);
                ah[mi][3] = __float_as_uint(Ph[(r0 + 8) * APAD + kc + 4]);
                al[mi][0] = __float_as_uint(Pl[r0 * APAD + kc]);
                al[mi][1] = __float_as_uint(Pl[(r0 + 8) * APAD + kc]);
                al[mi][2] = __float_as_uint(Pl[r0 * APAD + kc + 4]);
                al[mi][3] = __float_as_uint(Pl[(r0 + 8) * APAD + kc + 4]);
            }
#pragma unroll
            for (int ni = 0; ni < 4; ni++) {
                const int n0 = wn + ni * 8 + grp;
                uint32_t bh[2], bl[2];
                bh[0] = __float_as_uint(Vh[(ks * 8 + tig) * APAD + n0]);
                bh[1] = __float_as_uint(Vh[(ks * 8 + tig + 4) * APAD + n0]);
                bl[0] = __float_as_uint(Vl[(ks * 8 + tig) * APAD + n0]);
                bl[1] = __float_as_uint(Vl[(ks * 8 + tig + 4) * APAD + n0]);
#pragma unroll
                for (int mi = 0; mi < 2; mi++) {
                    mma_tf32(o[mi][ni], ah[mi], bh);
                    mma_tf32(o[mi][ni], ah[mi], bl);
                    mma_tf32(o[mi][ni], al[mi], bh);
                }
            }
        }
    }

    // ---- epilogue: normalize, write (B, S, D) layout ----
#pragma unroll
    for (int mi = 0; mi < 2; mi++)
#pragma unroll
        for (int hf = 0; hf < 2; hf++) {
            const float inv = 1.f / l_i[mi][hf];
            const int srow = qi * QT + wm + mi * 16 + grp + hf * 8;
#pragma unroll
            for (int ni = 0; ni < 4; ni++) {
                const int col = h * DK + wn + ni * 8 + tig * 2;
                float2 v = make_float2(o[mi][ni][hf * 2 + 0] * inv,
                                       o[mi][ni][hf * 2 + 1] * inv);
                *(float2*)&g_attn[((size_t)(b * SEQ) + srow) * DM + col] = v;
            }
        }
}

// ---------------------------------------------------------------------------

extern "C" void kernel_launch(void* const* d_in, const int* in_sizes, int n_in,
                              void* d_out, int out_size)
{
    const float* x  = (const float*)d_in[0];
    const float* Wq = (const float*)d_in[1];
    const float* bq = (const float*)d_in[2];
    const float* Wk = (const float*)d_in[3];
    const float* bk = (const float*)d_in[4];
    const float* Wv = (const float*)d_in[5];
    const float* bv = (const float*)d_in[6];
    const float* Wo = (const float*)d_in[7];
    const float* bo = (const float*)d_in[8];
    float* out = (float*)d_out;

    float *qp, *kp, *vp, *ap;
    cudaGetSymbolAddress((void**)&qp, g_q);
    cudaGetSymbolAddress((void**)&kp, g_k);
    cudaGetSymbolAddress((void**)&vp, g_v);
    cudaGetSymbolAddress((void**)&ap, g_attn);

    const dim3 ggrid(DM / 128, MTOT / 128);
    const int gemm_smem = 4 * 32 * LDA * (int)sizeof(float);

    cudaFuncSetAttribute(gemm_tf32<true>,  cudaFuncAttributeMaxDynamicSharedMemorySize, gemm_smem);
    cudaFuncSetAttribute(gemm_tf32<false>, cudaFuncAttributeMaxDynamicSharedMemorySize, gemm_smem);

    gemm_tf32<true><<<ggrid, 256, gemm_smem>>>(x, Wq, bq, qp);
    gemm_tf32<true><<<ggrid, 256, gemm_smem>>>(x, Wk, bk, kp);
    gemm_tf32<true><<<ggrid, 256, gemm_smem>>>(x, Wv, bv, vp);

    // attn smem: Q(2) + K(2) + V(2) + P(2) tiles + 2 reduce buffers
    const int attn_smem = (2 * QT * APAD + 4 * KT * APAD + 2 * QT * APAD + 4 * QT)
                          * (int)sizeof(float);   // 210,944 B
    cudaFuncSetAttribute(attn_mma, cudaFuncAttributeMaxDynamicSharedMemorySize,
                         attn_smem);
    attn_mma<<<dim3(SEQ / QT, NH, BATCH), 256, attn_smem>>>();

    gemm_tf32<false><<<ggrid, 256, gemm_smem>>>(ap, Wo, bo, out);
}